// round 13
// baseline (speedup 1.0000x reference)
#include <cuda_runtime.h>
#include <cstdint>
#include <cstddef>

// GraphAttentionLayer: N=12288, IN_F=256, OUT_F=128
// out = [h_prime (N*128 f32) | attention (N*N f32)]

constexpr int N_  = 12288;
constexpr int INF = 256;
constexpr int OF  = 128;
constexpr float SLOPE = 0.2f;

// ---- k_main tiling (warp-level single-pass tf32 mma.sync) ----
constexpr int RT = 128;             // rows per CTA (MMA M)
constexpr int KT = 32;              // j per tile
constexpr int NSPLIT = 3;           // 96*3 = 288 CTAs = one occ-2 wave
constexpr int JSEG = N_ / NSPLIT;   // 4096
constexpr int NTILE = JSEG / KT;    // 128

// smem stage: A and B tiles, 128 rows x 128B each, NO padding.
// Conflict-free via chunk swizzle: phys16B = logical16B ^ g(row&7),
// g = [0,3,4,7,1,2,5,6]  (verified CF for STS.128 stores, LDS.128
// fragment loads, and cp.async writes under octet phasing).
constexpr int A_OFF = 0;                     // p    [128 r x 32 f32]
constexpr int B_OFF = 128 * 128;             // htT  [128 c x 32 f32]
constexpr int STAGE_BYTES = 2 * 128 * 128;   // 32768
constexpr int DYN_SMEM = 2 * STAGE_BYTES;    // 65536
#define GLUT(r) ((0x65217430u >> (((r) & 7) * 4)) & 7u)

// ---- scratch (static device arrays; no allocation allowed) ----
__device__ float g_ht[(size_t)N_ * OF];              // h @ W               6 MB
__device__ float g_htT_perm[(size_t)OF * N_];        // h_t^T tf32, k-perm  6 MB
__device__ float g_src[N_];
__device__ float g_tgt[N_];
__device__ float g_Tmax;
__device__ float2 g_EF[N_];                          // (E_j, F_j) tables  96 KB
__device__ uint32_t g_mask[(size_t)N_ * N_ / 32];    // adj bits (pos order)
__device__ float g_Zp[NSPLIT * N_];                  // partial Z per split
__device__ float g_hp[(size_t)NSPLIT * N_ * OF];     // partial h_prime
__device__ float g_invZ[N_];

// ============================================================
// helpers
// ============================================================
__device__ __forceinline__ uint32_t cvta_smem(const void* p) {
    uint32_t a;
    asm("{ .reg .u64 t; cvta.to.shared.u64 t, %1; cvt.u32.u64 %0, t; }" : "=r"(a) : "l"(p));
    return a;
}
__device__ __forceinline__ uint32_t f2tf32(float v) {
    uint32_t u;
    asm("cvt.rna.tf32.f32 %0, %1;" : "=r"(u) : "f"(v));
    return u;
}
__device__ __forceinline__ void lds128(uint32_t r[4], uint32_t addr) {
    asm volatile("ld.shared.v4.b32 {%0,%1,%2,%3}, [%4];"
                 : "=r"(r[0]), "=r"(r[1]), "=r"(r[2]), "=r"(r[3]) : "r"(addr));
}
__device__ __forceinline__ void sts128(uint32_t addr, uint32_t a, uint32_t b,
                                       uint32_t c, uint32_t d) {
    asm volatile("st.shared.v4.b32 [%0], {%1,%2,%3,%4};"
                 :: "r"(addr), "r"(a), "r"(b), "r"(c), "r"(d));
}
// mma m16n8k8 tf32 -> f32, D += A*B
__device__ __forceinline__ void mma_tf32(float c[4], uint32_t a0, uint32_t a1,
                                         uint32_t a2, uint32_t a3,
                                         uint32_t b0, uint32_t b1) {
    asm volatile(
        "mma.sync.aligned.m16n8k8.row.col.f32.tf32.tf32.f32 "
        "{%0,%1,%2,%3}, {%4,%5,%6,%7}, {%8,%9}, {%0,%1,%2,%3};"
        : "+f"(c[0]), "+f"(c[1]), "+f"(c[2]), "+f"(c[3])
        : "r"(a0), "r"(a1), "r"(a2), "r"(a3), "r"(b0), "r"(b1));
}
__device__ __forceinline__ void cp_async16(uint32_t smem_dst, const void* gsrc) {
    asm volatile("cp.async.ca.shared.global [%0], [%1], 16;"
                 :: "r"(smem_dst), "l"(gsrc) : "memory");
}

// ============================================================
// Kernel 1: h_t = h @ W; epilogue writes k-interleaved tf32 h_t^T
// ============================================================
__global__ __launch_bounds__(256) void k_ht(const float* __restrict__ h, const float* __restrict__ W) {
    extern __shared__ float sm[];
    float* As = sm;             // 64*32
    float* Bs = sm + 2048;      // 32*128
    const int t = threadIdx.x, tx = t & 31, ty = t >> 5;
    const int r0 = blockIdx.x * 64;
    float4 acc[8];
#pragma unroll
    for (int r = 0; r < 8; ++r) acc[r] = make_float4(0.f, 0.f, 0.f, 0.f);

    for (int k0 = 0; k0 < INF; k0 += 32) {
#pragma unroll
        for (int k = 0; k < 2; ++k) {
            int id = t + k * 256;
            int row = id >> 3, c4 = id & 7;
            reinterpret_cast<float4*>(As)[id] =
                *reinterpret_cast<const float4*>(h + (size_t)(r0 + row) * INF + k0 + c4 * 4);
        }
#pragma unroll
        for (int k = 0; k < 4; ++k) {
            int id = t + k * 256;
            int row = id >> 5, c4 = id & 31;
            reinterpret_cast<float4*>(Bs)[id] =
                *reinterpret_cast<const float4*>(W + (size_t)(k0 + row) * OF + c4 * 4);
        }
        __syncthreads();
#pragma unroll
        for (int kk = 0; kk < 32; ++kk) {
            float4 b = reinterpret_cast<const float4*>(Bs)[kk * 32 + tx];
#pragma unroll
            for (int r = 0; r < 8; ++r) {
                float a = As[(ty * 8 + r) * 32 + kk];
                acc[r].x = fmaf(a, b.x, acc[r].x);
                acc[r].y = fmaf(a, b.y, acc[r].y);
                acc[r].z = fmaf(a, b.z, acc[r].z);
                acc[r].w = fmaf(a, b.w, acc[r].w);
            }
        }
        __syncthreads();
    }
#pragma unroll
    for (int r = 0; r < 8; ++r)
        *reinterpret_cast<float4*>(&g_ht[(size_t)(r0 + ty * 8 + r) * OF + tx * 4]) = acc[r];

    // epilogue: transpose, tf32-round, k-interleave (pos(j)=(j&3)*8+(j>>2))
    __syncthreads();
    float* ts = sm;                         // 64 x 136 f32 (reuse)
#pragma unroll
    for (int r = 0; r < 8; ++r) {
        int jl = ty * 8 + r;
        *reinterpret_cast<float4*>(&ts[jl * 136 + tx * 4]) = acc[r];
    }
    __syncthreads();
    const int lane = tx;
    for (int seg = ty; seg < 256; seg += 8) {
        int c = seg >> 1, grp = seg & 1;
        int jl = grp * 32 + ((lane & 7) << 2) + (lane >> 3);   // j(pos=lane)
        float v = ts[jl * 136 + c];
        g_htT_perm[(size_t)c * N_ + r0 + grp * 32 + lane] = __uint_as_float(f2tf32(v));
    }
}

// ============================================================
// Kernel 2: src = h_t @ a[:128], tgt = h_t @ a[128:]
// ============================================================
__global__ __launch_bounds__(256) void k_srctgt(const float* __restrict__ a) {
    const int t = threadIdx.x;
    const int lane = t & 31;
    const int row = blockIdx.x * 8 + (t >> 5);
    float4 hv = *reinterpret_cast<const float4*>(g_ht + (size_t)row * OF + lane * 4);
    float4 a1 = *reinterpret_cast<const float4*>(a + lane * 4);
    float4 a2 = *reinterpret_cast<const float4*>(a + OF + lane * 4);
    float s1 = hv.x * a1.x + hv.y * a1.y + hv.z * a1.z + hv.w * a1.w;
    float s2 = hv.x * a2.x + hv.y * a2.y + hv.z * a2.z + hv.w * a2.w;
#pragma unroll
    for (int off = 16; off > 0; off >>= 1) {
        s1 += __shfl_xor_sync(0xffffffffu, s1, off);
        s2 += __shfl_xor_sync(0xffffffffu, s2, off);
    }
    if (lane == 0) { g_src[row] = s1; g_tgt[row] = s2; }
}

// ============================================================
// Kernel 3: Tmax = max(tgt), then EF tables
// ============================================================
__global__ void k_tmaxef() {
    __shared__ float red[1024];
    const int t = threadIdx.x;
    float m = -3.402823466e38f;
    for (int i = t; i < N_; i += 1024) m = fmaxf(m, g_tgt[i]);
    red[t] = m;
    __syncthreads();
    for (int s = 512; s > 0; s >>= 1) {
        if (t < s) red[t] = fmaxf(red[t], red[t + s]);
        __syncthreads();
    }
    float Tm = red[0];
    if (t == 0) g_Tmax = Tm;
    for (int j = t; j < N_; j += 1024) {
        float tm = g_tgt[j] - Tm;
        g_EF[j] = make_float2(__expf(tm), __expf(0.2f * tm));
    }
}

// ============================================================
// Kernel 4 (main): conflict-free swizzled smem + tf32 mma
// ============================================================
__global__ __launch_bounds__(256, 2) void k_main(const int* __restrict__ adj) {
    extern __shared__ char smem[];
    const uint32_t sbase = cvta_smem(smem);

    const int t = threadIdx.x;
    const int lane = t & 31, wid = t >> 5;
    const int rb = blockIdx.x / NSPLIT;     // row block 0..95
    const int sp = blockIdx.x % NSPLIT;     // j split 0..2
    const int jbase = sp * JSEG;

    // phase-A identity: thread (row, h); h picks j-halves [16h,16h+16)
    const int row = t >> 1, h = t & 1;
    const int grow = rb * RT + row;
    const float srcv = g_src[grow];
    float e0 = srcv + g_Tmax;
    const float mv = fmaxf(e0, SLOPE * e0);
    const float Cc = __expf(e0 - mv);
    const float Dc = __expf(SLOPE * e0 - mv);
    const float Gc = __expf(-e0);
    float zacc = 0.f;
    const uint32_t grow_lut = GLUT(row);
    const uint32_t a_row = (uint32_t)row << 7;      // row*128 bytes
    const int h16 = h * 16;

    // B staging identity: thread (bcol, bhb): chunks {2k+bhb : k}
    const int bcol = t >> 1, bhb = t & 1;
    const uint32_t gb = GLUT(bcol);
    const float* bsrc_base = g_htT_perm + (size_t)bcol * N_ + jbase;
    const uint32_t bdst_row = (uint32_t)(B_OFF + (bcol << 7));

    // fragment identities
    const int wrow = wid >> 1, wcol = wid & 1;      // 4x2 warp grid
    const int fg = lane >> 2, t4 = lane & 3;
    const uint32_t gfg = GLUT(fg);
    const uint32_t ch0 = ((uint32_t)(2 * t4 + 0) ^ gfg) << 4;
    const uint32_t ch1 = ((uint32_t)(2 * t4 + 1) ^ gfg) << 4;

    float acc[2][8][4];
#pragma unroll
    for (int m = 0; m < 2; ++m)
#pragma unroll
        for (int n = 0; n < 8; ++n)
#pragma unroll
            for (int k = 0; k < 4; ++k) acc[m][n][k] = 0.f;

    // prefetch adj for tile 0 (thread's 16 contiguous j at jbase+16h)
    int4 padj[4];
    {
        const int4* ap = reinterpret_cast<const int4*>(adj + (size_t)grow * N_ + jbase + h16);
#pragma unroll
        for (int i = 0; i < 4; ++i) padj[i] = ap[i];
    }

    uint32_t mw[4];     // mask words (pos-bit order), flushed every 4 tiles

    for (int tt = 0; tt < NTILE; ++tt) {
        const uint32_t stage = sbase + (uint32_t)(tt & 1) * STAGE_BYTES;
        const int j0 = jbase + tt * KT;

        // ---- B tile: cp.async, swizzled dst (CF) ----
        {
            const float* src = bsrc_base + tt * 32;
            uint32_t dst = stage - sbase + bdst_row;   // offset form
#pragma unroll
            for (int k = 0; k < 4; ++k) {
                uint32_t lc = 2 * k + bhb;
                cp_async16(sbase + dst + ((lc ^ gb) << 4), src + lc * 4);
            }
            asm volatile("cp.async.commit_group;" ::: "memory");
        }

        // ---- phase A: p for 16 contiguous j; store 4x STS.128 (CF) ----
        {
            const float4* ef4 = reinterpret_cast<const float4*>(g_EF + j0 + h16);
            float pv[16];
            uint32_t mbits = 0;
#pragma unroll
            for (int c4 = 0; c4 < 4; ++c4) {
                const int* av = reinterpret_cast<const int*>(&padj[c4]);
                float4 efA = ef4[c4 * 2];
                float4 efB = ef4[c4 * 2 + 1];
                float Ev[4] = {efA.x, efA.z, efB.x, efB.z};
                float Fv[4] = {efA.y, efA.w, efB.y, efB.w};
#pragma unroll
                for (int u = 0; u < 4; ++u) {
                    int j16 = c4 * 4 + u;
                    bool pos = Ev[u] >= Gc;
                    float p  = (pos ? Cc : Dc) * (pos ? Ev[u] : Fv[u]);
                    bool on  = av[u] > 0;
                    p = on ? p : 0.f;
                    // bit position: pos(j) = (j16&3)*8 + 4h + (j16>>2)
                    mbits |= (on ? 1u : 0u) << ((j16 & 3) * 8 + 4 * h + (j16 >> 2));
                    pv[j16] = p;
                    zacc += p;
                }
            }
            uint32_t other = __shfl_xor_sync(0xffffffffu, mbits, 1);
            mw[tt & 3] = mbits | other;     // halves' bits are disjoint
            if ((tt & 3) == 3 && h == 0) {
                *reinterpret_cast<uint4*>(
                    g_mask + (size_t)grow * (N_ / 32) + (jbase >> 5) + (tt - 3)) =
                    make_uint4(mw[0], mw[1], mw[2], mw[3]);
            }
            // store per q: chunk logical = 2q+h, elems = pv[q], pv[4+q], pv[8+q], pv[12+q]
#pragma unroll
            for (int q = 0; q < 4; ++q) {
                uint32_t phys = ((uint32_t)(2 * q + h) ^ grow_lut) << 4;
                sts128(stage + a_row + phys,
                       f2tf32(pv[q]), f2tf32(pv[4 + q]), f2tf32(pv[8 + q]), f2tf32(pv[12 + q]));
            }
        }

        asm volatile("cp.async.wait_group 0;" ::: "memory");
        __syncthreads();

        // ---- prefetch adj for next tile ----
        if (tt + 1 < NTILE) {
            const int4* ap = reinterpret_cast<const int4*>(
                adj + (size_t)grow * N_ + jbase + (tt + 1) * KT + h16);
#pragma unroll
            for (int i = 0; i < 4; ++i) padj[i] = ap[i];
        }

        // ---- phase B: tf32 mma ----
        uint32_t aF[2][2][8];
#pragma unroll
        for (int mi = 0; mi < 2; ++mi) {
#pragma unroll
            for (int rh = 0; rh < 2; ++rh) {
                uint32_t rbase = stage + (uint32_t)((wrow * 32 + mi * 16 + rh * 8 + fg) << 7);
                lds128(&aF[mi][rh][0], rbase + ch0);
                lds128(&aF[mi][rh][4], rbase + ch1);
            }
        }
#pragma unroll
        for (int nc = 0; nc < 8; ++nc) {
            uint32_t bF[8];
            uint32_t cbase = stage + (uint32_t)B_OFF + (uint32_t)((wcol * 64 + nc * 8 + fg) << 7);
            lds128(&bF[0], cbase + ch0);
            lds128(&bF[4], cbase + ch1);
#pragma unroll
            for (int ks = 0; ks < 4; ++ks) {
#pragma unroll
                for (int mi = 0; mi < 2; ++mi) {
                    mma_tf32(acc[mi][nc],
                             aF[mi][0][2 * ks], aF[mi][1][2 * ks],
                             aF[mi][0][2 * ks + 1], aF[mi][1][2 * ks + 1],
                             bF[2 * ks], bF[2 * ks + 1]);
                }
            }
        }
    }

    // Zp: combine the two half-row threads
    float zsum = zacc + __shfl_xor_sync(0xffffffffu, zacc, 1);
    if (h == 0) g_Zp[sp * N_ + grow] = zsum;

    // epilogue: fragment -> g_hp partial
    const int er0 = rb * RT + wrow * 32 + fg;
    const int ec0 = wcol * 64 + 2 * t4;
#pragma unroll
    for (int mi = 0; mi < 2; ++mi) {
#pragma unroll
        for (int nc = 0; nc < 8; ++nc) {
            size_t base = ((size_t)sp * N_ + er0 + mi * 16) * OF + ec0 + nc * 8;
            *reinterpret_cast<float2*>(g_hp + base) = make_float2(acc[mi][nc][0], acc[mi][nc][1]);
            *reinterpret_cast<float2*>(g_hp + base + (size_t)8 * OF) = make_float2(acc[mi][nc][2], acc[mi][nc][3]);
        }
    }
}

// ============================================================
// Kernel 5: invZ[i] = 1 / sum_splits Zp
// ============================================================
__global__ void k_invz() {
    int i = blockIdx.x * 1024 + threadIdx.x;
    float z = 0.f;
#pragma unroll
    for (int s = 0; s < NSPLIT; ++s) z += g_Zp[s * N_ + i];
    g_invZ[i] = 1.0f / z;
}

// ============================================================
// Kernel 6: h_prime = (sum_splits hp_part) * invZ  -> d_out[0:N*OF]
// ============================================================
__global__ void k_merge(float* __restrict__ out) {
    size_t idx = (size_t)blockIdx.x * 1024 + threadIdx.x;
    int row = (int)(idx >> 7);
    float s = 0.f;
#pragma unroll
    for (int p = 0; p < NSPLIT; ++p) s += g_hp[(size_t)p * N_ * OF + idx];
    out[idx] = s * g_invZ[row];
}

// ============================================================
// Kernel 7: attention from bitmask (pos-order) + separable exp
// ============================================================
__global__ __launch_bounds__(256) void k_attn(float* __restrict__ out) {
    __shared__ uint32_t msk[N_ / 32];   // 1.5 KB
    const int row = blockIdx.x;
    const int t = threadIdx.x;
    for (int i = t; i < N_ / 32; i += 256)
        msk[i] = g_mask[(size_t)row * (N_ / 32) + i];

    const float sv = g_src[row];
    float e0 = sv + g_Tmax;
    const float m  = fmaxf(e0, SLOPE * e0);
    const float iz = g_invZ[row];
    const float Cc = __expf(e0 - m) * iz;
    const float Dc = __expf(SLOPE * e0 - m) * iz;
    const float Gc = __expf(-e0);
    __syncthreads();

    const float4* ef4 = reinterpret_cast<const float4*>(g_EF);
    float4* orow = reinterpret_cast<float4*>(out + (size_t)row * N_);
#pragma unroll
    for (int it = 0; it < N_ / 4 / 256; ++it) {
        int j4 = it * 256 + t;                        // j = 4*j4 + r
        float4 efA = __ldg(ef4 + j4 * 2);
        float4 efB = __ldg(ef4 + j4 * 2 + 1);
        // pos-order bits: j = 32w + 4m + r -> bit r*8 + m; m = j4&7
        uint32_t w = msk[j4 >> 3] >> (j4 & 7);
        float4 o;
        bool pos; float p;
        pos = efA.x >= Gc; p = (pos ? Cc : Dc) * (pos ? efA.x : efA.y); o.x = (w & 1u)         ? p : 0.f;
        pos = efA.z >= Gc; p = (pos ? Cc : Dc) * (pos ? efA.z : efA.w); o.y = ((w >> 8) & 1u)  ? p : 0.f;
        pos = efB.x >= Gc; p = (pos ? Cc : Dc) * (pos ? efB.x : efB.y); o.z = ((w >> 16) & 1u) ? p : 0.f;
        pos = efB.z >= Gc; p = (pos ? Cc : Dc) * (pos ? efB.z : efB.w); o.w = ((w >> 24) & 1u) ? p : 0.f;
        orow[j4] = o;
    }
}

// ============================================================
extern "C" void kernel_launch(void* const* d_in, const int* in_sizes, int n_in,
                              void* d_out, int out_size) {
    const float* h   = (const float*)d_in[0];
    const int*   adj = (const int*)d_in[1];
    const float* W   = (const float*)d_in[2];
    const float* a   = (const float*)d_in[3];
    float* out = (float*)d_out;

    cudaFuncSetAttribute(k_main, cudaFuncAttributeMaxDynamicSharedMemorySize, DYN_SMEM);

    constexpr int HT_SMEM = 64 * 136 * 4;   // 34816 (>= As+Bs 24576)

    k_ht<<<N_ / 64, 256, HT_SMEM>>>(h, W);        // launch 1
    k_srctgt<<<N_ / 8, 256>>>(a);                 // launch 2
    k_tmaxef<<<1, 1024>>>();                      // launch 3
    k_main<<<(N_ / RT) * NSPLIT, 256, DYN_SMEM>>>(adj);   // launch 4 (ncu slot)
    k_invz<<<N_ / 1024, 1024>>>();                // launch 5
    k_merge<<<(N_ * OF) / 1024, 1024>>>(out);     // launch 6
    k_attn<<<N_, 256>>>(out + (size_t)N_ * OF);   // launch 7
}

// round 15
// speedup vs baseline: 1.3970x; 1.3970x over previous
#include <cuda_runtime.h>
#include <cstdint>
#include <cstddef>

// GraphAttentionLayer: N=12288, IN_F=256, OUT_F=128
// out = [h_prime (N*128 f32) | attention (N*N f32)]

constexpr int N_  = 12288;
constexpr int INF = 256;
constexpr int OF  = 128;
constexpr float SLOPE = 0.2f;

// ---- k_main tiling (warp-level single-pass tf32 mma.sync) ----
constexpr int RT = 128;             // rows per CTA (MMA M)
constexpr int KT = 32;              // j per tile
constexpr int NSPLIT = 3;           // 96*3 = 288 CTAs = one occ-2 wave
constexpr int JSEG = N_ / NSPLIT;   // 4096
constexpr int NTILE = JSEG / KT;    // 128

// smem stage (R11 layout, proven): rows of 32 f32 + 4 f32 pad = 144B.
// Fragment LDS.128 are conflict-free (banks 4*fg+8*t4). j-dim stored
// k-interleaved: pos(j) = (j&3)*8 + (j>>2), so tf32 fragments are
// contiguous AND phase-A stores vectorize to 4x STS.128 (2-way).
constexpr int ROWB = 144;
constexpr int A_OFF = 0;                     // p    [128 r x 32 f32]
constexpr int B_OFF = 128 * ROWB;            // htT  [128 c x 32 f32]
constexpr int STAGE_BYTES = 2 * 128 * ROWB;  // 36864
constexpr int DYN_SMEM = 2 * STAGE_BYTES;    // 73728

// ---- scratch (static device arrays; no allocation allowed) ----
__device__ float g_ht[(size_t)N_ * OF];              // h @ W               6 MB
__device__ float g_htT_perm[(size_t)OF * N_];        // h_t^T tf32, k-perm  6 MB
__device__ float g_src[N_];
__device__ float g_tgt[N_];
__device__ float g_Tmax;
__device__ float2 g_EF[N_];                          // (E_j, F_j) tables  96 KB
__device__ uint32_t g_mask[(size_t)N_ * N_ / 32];    // adj bitmask        18.9 MB
__device__ float g_Zp[NSPLIT * N_];                  // partial Z per split
__device__ float g_hp[(size_t)NSPLIT * N_ * OF];     // partial h_prime    18.9 MB
__device__ float g_invZ[N_];

// ============================================================
// helpers
// ============================================================
__device__ __forceinline__ uint32_t cvta_smem(const void* p) {
    uint32_t a;
    asm("{ .reg .u64 t; cvta.to.shared.u64 t, %1; cvt.u32.u64 %0, t; }" : "=r"(a) : "l"(p));
    return a;
}
__device__ __forceinline__ uint32_t f2tf32(float v) {
    uint32_t u;
    asm("cvt.rna.tf32.f32 %0, %1;" : "=r"(u) : "f"(v));
    return u;
}
__device__ __forceinline__ void lds128(uint32_t r[4], uint32_t addr) {
    asm volatile("ld.shared.v4.b32 {%0,%1,%2,%3}, [%4];"
                 : "=r"(r[0]), "=r"(r[1]), "=r"(r[2]), "=r"(r[3]) : "r"(addr));
}
__device__ __forceinline__ void sts128(uint32_t addr, uint32_t a, uint32_t b,
                                       uint32_t c, uint32_t d) {
    asm volatile("st.shared.v4.b32 [%0], {%1,%2,%3,%4};"
                 :: "r"(addr), "r"(a), "r"(b), "r"(c), "r"(d));
}
// mma m16n8k8 tf32 -> f32, D += A*B
__device__ __forceinline__ void mma_tf32(float c[4], uint32_t a0, uint32_t a1,
                                         uint32_t a2, uint32_t a3,
                                         uint32_t b0, uint32_t b1) {
    asm volatile(
        "mma.sync.aligned.m16n8k8.row.col.f32.tf32.tf32.f32 "
        "{%0,%1,%2,%3}, {%4,%5,%6,%7}, {%8,%9}, {%0,%1,%2,%3};"
        : "+f"(c[0]), "+f"(c[1]), "+f"(c[2]), "+f"(c[3])
        : "r"(a0), "r"(a1), "r"(a2), "r"(a3), "r"(b0), "r"(b1));
}
__device__ __forceinline__ void cp_async16(uint32_t smem_dst, const void* gsrc) {
    asm volatile("cp.async.ca.shared.global [%0], [%1], 16;"
                 :: "r"(smem_dst), "l"(gsrc) : "memory");
}

// ============================================================
// Kernel 1: h_t = h @ W; epilogue writes k-interleaved tf32 h_t^T
// ============================================================
__global__ __launch_bounds__(256) void k_ht(const float* __restrict__ h, const float* __restrict__ W) {
    extern __shared__ float sm[];
    float* As = sm;             // 64*32
    float* Bs = sm + 2048;      // 32*128
    const int t = threadIdx.x, tx = t & 31, ty = t >> 5;
    const int r0 = blockIdx.x * 64;
    float4 acc[8];
#pragma unroll
    for (int r = 0; r < 8; ++r) acc[r] = make_float4(0.f, 0.f, 0.f, 0.f);

    for (int k0 = 0; k0 < INF; k0 += 32) {
#pragma unroll
        for (int k = 0; k < 2; ++k) {
            int id = t + k * 256;
            int row = id >> 3, c4 = id & 7;
            reinterpret_cast<float4*>(As)[id] =
                *reinterpret_cast<const float4*>(h + (size_t)(r0 + row) * INF + k0 + c4 * 4);
        }
#pragma unroll
        for (int k = 0; k < 4; ++k) {
            int id = t + k * 256;
            int row = id >> 5, c4 = id & 31;
            reinterpret_cast<float4*>(Bs)[id] =
                *reinterpret_cast<const float4*>(W + (size_t)(k0 + row) * OF + c4 * 4);
        }
        __syncthreads();
#pragma unroll
        for (int kk = 0; kk < 32; ++kk) {
            float4 b = reinterpret_cast<const float4*>(Bs)[kk * 32 + tx];
#pragma unroll
            for (int r = 0; r < 8; ++r) {
                float a = As[(ty * 8 + r) * 32 + kk];
                acc[r].x = fmaf(a, b.x, acc[r].x);
                acc[r].y = fmaf(a, b.y, acc[r].y);
                acc[r].z = fmaf(a, b.z, acc[r].z);
                acc[r].w = fmaf(a, b.w, acc[r].w);
            }
        }
        __syncthreads();
    }
#pragma unroll
    for (int r = 0; r < 8; ++r)
        *reinterpret_cast<float4*>(&g_ht[(size_t)(r0 + ty * 8 + r) * OF + tx * 4]) = acc[r];

    // epilogue: transpose, tf32-round, k-interleave (pos(j)=(j&3)*8+(j>>2))
    __syncthreads();
    float* ts = sm;                         // 64 x 136 f32 (reuse)
#pragma unroll
    for (int r = 0; r < 8; ++r) {
        int jl = ty * 8 + r;
        *reinterpret_cast<float4*>(&ts[jl * 136 + tx * 4]) = acc[r];
    }
    __syncthreads();
    const int lane = tx;
    for (int seg = ty; seg < 256; seg += 8) {
        int c = seg >> 1, grp = seg & 1;
        int jl = grp * 32 + ((lane & 7) << 2) + (lane >> 3);   // j(pos=lane)
        float v = ts[jl * 136 + c];
        g_htT_perm[(size_t)c * N_ + r0 + grp * 32 + lane] = __uint_as_float(f2tf32(v));
    }
}

// ============================================================
// Kernel 2: src = h_t @ a[:128], tgt = h_t @ a[128:]
// ============================================================
__global__ __launch_bounds__(256) void k_srctgt(const float* __restrict__ a) {
    const int t = threadIdx.x;
    const int lane = t & 31;
    const int row = blockIdx.x * 8 + (t >> 5);
    float4 hv = *reinterpret_cast<const float4*>(g_ht + (size_t)row * OF + lane * 4);
    float4 a1 = *reinterpret_cast<const float4*>(a + lane * 4);
    float4 a2 = *reinterpret_cast<const float4*>(a + OF + lane * 4);
    float s1 = hv.x * a1.x + hv.y * a1.y + hv.z * a1.z + hv.w * a1.w;
    float s2 = hv.x * a2.x + hv.y * a2.y + hv.z * a2.z + hv.w * a2.w;
#pragma unroll
    for (int off = 16; off > 0; off >>= 1) {
        s1 += __shfl_xor_sync(0xffffffffu, s1, off);
        s2 += __shfl_xor_sync(0xffffffffu, s2, off);
    }
    if (lane == 0) { g_src[row] = s1; g_tgt[row] = s2; }
}

// ============================================================
// Kernel 3: Tmax = max(tgt), then EF tables
// ============================================================
__global__ void k_tmaxef() {
    __shared__ float red[1024];
    const int t = threadIdx.x;
    float m = -3.402823466e38f;
    for (int i = t; i < N_; i += 1024) m = fmaxf(m, g_tgt[i]);
    red[t] = m;
    __syncthreads();
    for (int s = 512; s > 0; s >>= 1) {
        if (t < s) red[t] = fmaxf(red[t], red[t + s]);
        __syncthreads();
    }
    float Tm = red[0];
    if (t == 0) g_Tmax = Tm;
    for (int j = t; j < N_; j += 1024) {
        float tm = g_tgt[j] - Tm;
        g_EF[j] = make_float2(__expf(tm), __expf(0.2f * tm));
    }
}

// ============================================================
// Kernel 4 (main): R11-proven layout; phase-A stores vectorized
// to 4x STS.128 (identical data placement, 2-way vs 4-way banks)
// ============================================================
__global__ __launch_bounds__(256, 2) void k_main(const int* __restrict__ adj) {
    extern __shared__ char smem[];
    const uint32_t sbase = cvta_smem(smem);

    const int t = threadIdx.x;
    const int lane = t & 31, wid = t >> 5;
    const int rb = blockIdx.x / NSPLIT;     // row block 0..95
    const int sp = blockIdx.x % NSPLIT;     // j split 0..2
    const int jbase = sp * JSEG;

    // phase-A identity: 2 threads per row, 16 contiguous j each
    const int row = t >> 1, half = t & 1;
    const int grow = rb * RT + row;
    const float srcv = g_src[grow];
    float e0 = srcv + g_Tmax;
    const float mv = fmaxf(e0, SLOPE * e0);
    const float Cc = __expf(e0 - mv);
    const float Dc = __expf(SLOPE * e0 - mv);
    const float Gc = __expf(-e0);
    float zacc = 0.f;
    const uint32_t a_row_base = sbase + A_OFF + (uint32_t)row * ROWB + half * 16;
    const int h16 = half * 16;

    // B staging via cp.async: thread -> row c = t>>1, 4 chunks of 16B
    const int bc = t >> 1, bq0 = (t & 1) * 4;

    // fragment identities
    const int wrow = wid >> 1, wcol = wid & 1;          // 4x2 warp grid
    const int fg = lane >> 2, t4 = lane & 3;
    const uint32_t a_frag = A_OFF + (uint32_t)(wrow * 32 + fg) * ROWB + t4 * 32;
    const uint32_t b_frag = B_OFF + (uint32_t)(wcol * 64 + fg) * ROWB + t4 * 32;

    float acc[2][8][4];
#pragma unroll
    for (int m = 0; m < 2; ++m)
#pragma unroll
        for (int n = 0; n < 8; ++n)
#pragma unroll
            for (int k = 0; k < 4; ++k) acc[m][n][k] = 0.f;

    // prefetch adj for tile 0
    int4 padj[4];
    {
        const int4* ap = reinterpret_cast<const int4*>(adj + (size_t)grow * N_ + jbase + h16);
#pragma unroll
        for (int i = 0; i < 4; ++i) padj[i] = ap[i];
    }

    uint32_t mw[4];     // packed mask words, flushed every 4 tiles (half==0)

    for (int tt = 0; tt < NTILE; ++tt) {
        const uint32_t stage = sbase + (uint32_t)(tt & 1) * STAGE_BYTES;
        const int j0 = jbase + tt * KT;

        // ---- B tile: cp.async (overlaps with phase A below) ----
        {
            const float* src = g_htT_perm + (size_t)bc * N_ + j0 + bq0 * 4;
            uint32_t dst = stage + B_OFF + bc * ROWB + bq0 * 16;
#pragma unroll
            for (int q = 0; q < 4; ++q)
                cp_async16(dst + q * 16, src + q * 4);
            asm volatile("cp.async.commit_group;" ::: "memory");
        }

        // ---- phase A: p for 16 contiguous j; mask bits; 4x STS.128 ----
        {
            const float4* ef4 = reinterpret_cast<const float4*>(g_EF + j0 + h16);
            float pv[16];
            uint32_t mbits = 0;
#pragma unroll
            for (int c4 = 0; c4 < 4; ++c4) {
                const int* av = reinterpret_cast<const int*>(&padj[c4]);
                float4 efA = ef4[c4 * 2];
                float4 efB = ef4[c4 * 2 + 1];
                float Ev[4] = {efA.x, efA.z, efB.x, efB.z};
                float Fv[4] = {efA.y, efA.w, efB.y, efB.w};
#pragma unroll
                for (int u = 0; u < 4; ++u) {
                    bool pos = Ev[u] >= Gc;
                    float p  = (pos ? Cc : Dc) * (pos ? Ev[u] : Fv[u]);
                    bool on  = av[u] > 0;
                    p = on ? p : 0.f;
                    mbits |= (on ? 1u : 0u) << (c4 * 4 + u);
                    pv[c4 * 4 + u] = p;
                    zacc += p;
                }
            }
            uint32_t other = __shfl_xor_sync(0xffffffffu, mbits, 1);
            mw[tt & 3] = half ? ((mbits << 16) | other) : (mbits | (other << 16));
            if ((tt & 3) == 3 && half == 0) {
                *reinterpret_cast<uint4*>(
                    g_mask + (size_t)grow * (N_ / 32) + (jbase >> 5) + (tt - 3)) =
                    make_uint4(mw[0], mw[1], mw[2], mw[3]);
            }
            // vectorized store, same placement as scalar k-interleave:
            // element e=q+4i -> pos (e&3)*8+4h+(e>>2) = 8q+4h+i
            // -> float4 {pv[q],pv[q+4],pv[q+8],pv[q+12]} at byte 32q (+16h in base)
            const uint32_t soff = stage - sbase;
#pragma unroll
            for (int q = 0; q < 4; ++q) {
                sts128(soff + a_row_base + q * 32,
                       f2tf32(pv[q]), f2tf32(pv[4 + q]), f2tf32(pv[8 + q]), f2tf32(pv[12 + q]));
            }
        }

        asm volatile("cp.async.wait_group 0;" ::: "memory");
        __syncthreads();

        // ---- prefetch adj for next tile (regs only, no hazard) ----
        if (tt + 1 < NTILE) {
            const int4* ap = reinterpret_cast<const int4*>(
                adj + (size_t)grow * N_ + jbase + (tt + 1) * KT + h16);
#pragma unroll
            for (int i = 0; i < 4; ++i) padj[i] = ap[i];
        }

        // ---- phase B: single-pass tf32 mma ----
        uint32_t aF[2][2][8];   // [mi][rowhalf][2*ks + (0:a0/a1, 1:a2/a3)]
#pragma unroll
        for (int mi = 0; mi < 2; ++mi) {
#pragma unroll
            for (int rh = 0; rh < 2; ++rh) {
                uint32_t ab = stage + a_frag + (uint32_t)(mi * 16 + rh * 8) * ROWB;
                lds128(&aF[mi][rh][0], ab);
                lds128(&aF[mi][rh][4], ab + 16);
            }
        }
#pragma unroll
        for (int nc = 0; nc < 8; ++nc) {
            uint32_t bF[8];
            uint32_t bb = stage + b_frag + (uint32_t)(nc * 8) * ROWB;
            lds128(&bF[0], bb);
            lds128(&bF[4], bb + 16);
#pragma unroll
            for (int ks = 0; ks < 4; ++ks) {
#pragma unroll
                for (int mi = 0; mi < 2; ++mi) {
                    mma_tf32(acc[mi][nc],
                             aF[mi][0][2 * ks], aF[mi][1][2 * ks],
                             aF[mi][0][2 * ks + 1], aF[mi][1][2 * ks + 1],
                             bF[2 * ks], bF[2 * ks + 1]);
                }
            }
        }
    }

    // Zp: combine the two half-row threads
    float zsum = zacc + __shfl_xor_sync(0xffffffffu, zacc, 1);
    if (half == 0) g_Zp[sp * N_ + grow] = zsum;

    // epilogue: fragment -> g_hp partial
    const int er0 = rb * RT + wrow * 32 + fg;
    const int ec0 = wcol * 64 + 2 * t4;
#pragma unroll
    for (int mi = 0; mi < 2; ++mi) {
#pragma unroll
        for (int nc = 0; nc < 8; ++nc) {
            size_t base = ((size_t)sp * N_ + er0 + mi * 16) * OF + ec0 + nc * 8;
            *reinterpret_cast<float2*>(g_hp + base) = make_float2(acc[mi][nc][0], acc[mi][nc][1]);
            *reinterpret_cast<float2*>(g_hp + base + (size_t)8 * OF) = make_float2(acc[mi][nc][2], acc[mi][nc][3]);
        }
    }
}

// ============================================================
// Kernel 5: invZ[i] = 1 / sum_splits Zp
// ============================================================
__global__ void k_invz() {
    int i = blockIdx.x * 1024 + threadIdx.x;
    float z = 0.f;
#pragma unroll
    for (int s = 0; s < NSPLIT; ++s) z += g_Zp[s * N_ + i];
    g_invZ[i] = 1.0f / z;
}

// ============================================================
// Kernel 6: h_prime = (sum_splits hp_part) * invZ  -> d_out[0:N*OF]
// ============================================================
__global__ void k_merge(float* __restrict__ out) {
    size_t idx = (size_t)blockIdx.x * 1024 + threadIdx.x;
    int row = (int)(idx >> 7);
    float s = 0.f;
#pragma unroll
    for (int p = 0; p < NSPLIT; ++p) s += g_hp[(size_t)p * N_ * OF + idx];
    out[idx] = s * g_invZ[row];
}

// ============================================================
// Kernel 7: attention from bitmask + separable exp (write-bound)
// ============================================================
__global__ __launch_bounds__(256) void k_attn(float* __restrict__ out) {
    __shared__ uint32_t msk[N_ / 32];   // 1.5 KB
    const int row = blockIdx.x;
    const int t = threadIdx.x;
    for (int i = t; i < N_ / 32; i += 256)
        msk[i] = g_mask[(size_t)row * (N_ / 32) + i];

    const float sv = g_src[row];
    float e0 = sv + g_Tmax;
    const float m  = fmaxf(e0, SLOPE * e0);
    const float iz = g_invZ[row];
    const float Cc = __expf(e0 - m) * iz;
    const float Dc = __expf(SLOPE * e0 - m) * iz;
    const float Gc = __expf(-e0);
    __syncthreads();

    const float4* ef4 = reinterpret_cast<const float4*>(g_EF);
    float4* orow = reinterpret_cast<float4*>(out + (size_t)row * N_);
#pragma unroll
    for (int it = 0; it < N_ / 4 / 256; ++it) {
        int j4 = it * 256 + t;                        // j = 4*j4
        float4 efA = __ldg(ef4 + j4 * 2);
        float4 efB = __ldg(ef4 + j4 * 2 + 1);
        uint32_t w = msk[j4 >> 3] >> ((j4 & 7) * 4);
        float4 o;
        bool pos; float p;
        pos = efA.x >= Gc; p = (pos ? Cc : Dc) * (pos ? efA.x : efA.y); o.x = (w & 1u) ? p : 0.f;
        pos = efA.z >= Gc; p = (pos ? Cc : Dc) * (pos ? efA.z : efA.w); o.y = (w & 2u) ? p : 0.f;
        pos = efB.x >= Gc; p = (pos ? Cc : Dc) * (pos ? efB.x : efB.y); o.z = (w & 4u) ? p : 0.f;
        pos = efB.z >= Gc; p = (pos ? Cc : Dc) * (pos ? efB.z : efB.w); o.w = (w & 8u) ? p : 0.f;
        orow[j4] = o;
    }
}

// ============================================================
extern "C" void kernel_launch(void* const* d_in, const int* in_sizes, int n_in,
                              void* d_out, int out_size) {
    const float* h   = (const float*)d_in[0];
    const int*   adj = (const int*)d_in[1];
    const float* W   = (const float*)d_in[2];
    const float* a   = (const float*)d_in[3];
    float* out = (float*)d_out;

    cudaFuncSetAttribute(k_main, cudaFuncAttributeMaxDynamicSharedMemorySize, DYN_SMEM);

    constexpr int HT_SMEM = 64 * 136 * 4;   // 34816 (>= As+Bs 24576)

    k_ht<<<N_ / 64, 256, HT_SMEM>>>(h, W);        // launch 1
    k_srctgt<<<N_ / 8, 256>>>(a);                 // launch 2
    k_tmaxef<<<1, 1024>>>();                      // launch 3
    k_main<<<(N_ / RT) * NSPLIT, 256, DYN_SMEM>>>(adj);   // launch 4 (ncu slot)
    k_invz<<<N_ / 1024, 1024>>>();                // launch 5
    k_merge<<<(N_ * OF) / 1024, 1024>>>(out);     // launch 6
    k_attn<<<N_, 256>>>(out + (size_t)N_ * OF);   // launch 7
}